// round 10
// baseline (speedup 1.0000x reference)
#include <cuda_runtime.h>
#include <cstdint>

#define N_RES   20000
#define N_EDGE  640000
#define NUM_AA  21
#define FEAT    340
#define EPSV    1e-8f
#define EPB     8          // edges (warps) per block

// ---------------- device scratch (no mallocs allowed) ----------------
// g_bb4[r*4+k] = atom k (n,ca,c,cb); w-lanes carry metadata:
//   atom0.w = noised flag (0/1), atom1.w = int_as_float(seq)
__device__ float4 g_bb4[N_RES * 4];
// g_Rt4[r*4+c], c=0..2: column c of R = (R[0,c], R[1,c], R[2,c], 0)
//               c=3:    (t0, t1, t2, 0)
__device__ float4 g_Rt4[N_RES * 4];
__device__ float  g_local[N_RES * 12];  // R^T (bb - t)
// positional-encoding table: row (d+19999) = [cos(d*f0..f7), sin(d*f0..f7)]
__device__ float  g_pos[40224 * 16];

__constant__ float c_freq[8] = {
    1.0f, 0.31622776601683794f, 0.1f, 0.03162277660168379f,
    0.01f, 0.0031622776601683794f, 0.001f, 0.00031622776601683794f
};

#define RBF_DELTA 1.0666666666666667f    /* (4/3)*0.8 */
#define RBF_DSQ   1.1377777777777778f    /* delta^2 */
#define RBF_C     0.10274027f            /* exp(-2*delta^2) */

// ---------------- prep: mask dtype detection + residue geometry + pos table ----------------
// Mask dtype detection per-block from the first 512 words (= 2048 bytes,
// in-bounds under every interpretation of the 20000-element mask):
//   int32 0/1 mask   -> words all in {0,1}
//   float32 0/1 mask -> words all in {0, 0x3F800000}
//   packed bool      -> neither (P(ambiguous) = 8^-512 ~ 0)
__global__ void prep_kernel(const float* __restrict__ atom14,
                            const float* __restrict__ rig,
                            const int*   __restrict__ seq,
                            const void*  __restrict__ mask) {
    __shared__ int s_not01, s_notf;
    if (threadIdx.x == 0) { s_not01 = 0; s_notf = 0; }
    __syncthreads();
    {
        const unsigned int* mw = (const unsigned int*)mask;
        unsigned int v0 = mw[threadIdx.x];
        unsigned int v1 = mw[threadIdx.x + 256];
        int not01 = (v0 > 1u) | (v1 > 1u);
        int notf  = ((v0 != 0u && v0 != 0x3F800000u) ||
                     (v1 != 0u && v1 != 0x3F800000u));
        if (not01) atomicOr(&s_not01, 1);
        if (notf)  atomicOr(&s_notf, 1);
    }
    __syncthreads();
    int kind;                                // 0=bool(u8), 1=int32, 2=float32
    if (!s_notf)       kind = 2;
    else if (!s_not01) kind = 1;
    else               kind = 0;

    int tid = blockIdx.x * blockDim.x + threadIdx.x;   // 0 .. 20223

    // ---- positional table: rows tid and tid+20000 (covers 0..39999+) ----
    #pragma unroll
    for (int half = 0; half < 2; half++) {
        int rrow = tid + half * 20000;
        float dp = (float)(rrow - 19999);
        #pragma unroll
        for (int k = 0; k < 8; k++) {
            float ang = dp * c_freq[k];
            g_pos[rrow * 16 + k]     = cosf(ang);
            g_pos[rrow * 16 + 8 + k] = sinf(ang);
        }
    }

    int r = tid;
    if (r >= N_RES) return;

    const float* a = atom14 + (size_t)r * 42;   // 14 atoms * 3
    float n0 = a[0], n1 = a[1], n2 = a[2];
    float ca0 = a[3], ca1 = a[4], ca2 = a[5];
    float c0 = a[6], c1 = a[7], c2 = a[8];

    float b0 = ca0 - n0, b1 = ca1 - n1, b2 = ca2 - n2;
    float e0 = c0 - ca0, e1 = c1 - ca1, e2 = c2 - ca2;
    float ax = b1 * e2 - b2 * e1;
    float ay = b2 * e0 - b0 * e2;
    float az = b0 * e1 - b1 * e0;
    float cb0 = -0.58273431f * ax + 0.56802827f * b0 - 0.54067466f * e0 + ca0;
    float cb1 = -0.58273431f * ay + 0.56802827f * b1 - 0.54067466f * e1 + ca1;
    float cb2 = -0.58273431f * az + 0.56802827f * b2 - 0.54067466f * e2 + ca2;

    float noised;
    if (kind == 0)      noised = ((const unsigned char*)mask)[r] ? 1.f : 0.f;
    else if (kind == 1) noised = ((const int*)mask)[r] ? 1.f : 0.f;
    else                noised = (((const float*)mask)[r] != 0.f) ? 1.f : 0.f;

    float bb[12] = { n0, n1, n2, ca0, ca1, ca2, c0, c1, c2, cb0, cb1, cb2 };
    g_bb4[r * 4 + 0] = make_float4(n0, n1, n2, noised);
    g_bb4[r * 4 + 1] = make_float4(ca0, ca1, ca2, __int_as_float(seq[r]));
    g_bb4[r * 4 + 2] = make_float4(c0, c1, c2, 0.f);
    g_bb4[r * 4 + 3] = make_float4(cb0, cb1, cb2, 0.f);

    const float* q = rig + (size_t)r * 7;
    float qw = q[0], qx = q[1], qy = q[2], qz = q[3];
    float inv = rsqrtf(qw * qw + qx * qx + qy * qy + qz * qz);
    qw *= inv; qx *= inv; qy *= inv; qz *= inv;

    float R[9];
    R[0] = 1.f - 2.f * (qy * qy + qz * qz);
    R[1] = 2.f * (qx * qy - qw * qz);
    R[2] = 2.f * (qx * qz + qw * qy);
    R[3] = 2.f * (qx * qy + qw * qz);
    R[4] = 1.f - 2.f * (qx * qx + qz * qz);
    R[5] = 2.f * (qy * qz - qw * qx);
    R[6] = 2.f * (qx * qz - qw * qy);
    R[7] = 2.f * (qy * qz + qw * qx);
    R[8] = 1.f - 2.f * (qx * qx + qy * qy);
    float t0 = q[4], t1 = q[5], t2 = q[6];

    // column-major chunks: chunk c = (R[0,c], R[1,c], R[2,c], 0); chunk 3 = t
    g_Rt4[r * 4 + 0] = make_float4(R[0], R[3], R[6], 0.f);
    g_Rt4[r * 4 + 1] = make_float4(R[1], R[4], R[7], 0.f);
    g_Rt4[r * 4 + 2] = make_float4(R[2], R[5], R[8], 0.f);
    g_Rt4[r * 4 + 3] = make_float4(t0, t1, t2, 0.f);

    // local[k][i] = sum_j R[j][i] * (bb[k][j] - t[j])
    #pragma unroll
    for (int k = 0; k < 4; k++) {
        float vx = bb[k * 3 + 0] - t0;
        float vy = bb[k * 3 + 1] - t1;
        float vz = bb[k * 3 + 2] - t2;
        #pragma unroll
        for (int i = 0; i < 3; i++) {
            g_local[r * 12 + k * 3 + i] = R[0 + i] * vx + R[3 + i] * vy + R[6 + i] * vz;
        }
    }
}

// ---------------- per-edge feature kernel: 1 warp / edge, zero smem ----------------
__global__ __launch_bounds__(EPB * 32) void edge_kernel(
    const int* __restrict__ eidx,     // [2, N_EDGE]: row0=dst, row1=src
    float* __restrict__ out) {

    const unsigned FULL = 0xFFFFFFFFu;
    int lane = threadIdx.x & 31;
    int e    = blockIdx.x * EPB + (threadIdx.x >> 5);

    int dst = eidx[e];
    int src = eidx[N_EDGE + e];

    // register gathers (broadcast-heavy, L2-resident tables)
    float4 f4s = g_bb4[src * 4 + ((lane >> 2) & 3)];   // src atom (lane>>2)&3
    float4 f4d = g_bb4[dst * 4 + (lane & 3)];          // dst atom lane&3
    float4 f4rt = g_Rt4[src * 4 + (lane & 3)];         // chunk (lane&3): lanes 0-3 canonical
    float loc = g_local[src * 12 + min(lane, 11)];     // lanes 0-11 meaningful
    float pv  = g_pos[((dst - src) + 19999) * 16 + (lane & 15)];  // pos enc row

    // metadata via shuffle from w-lanes (no extra loads)
    float noised_src = __shfl_sync(FULL, f4s.w, 0);    // lane 0 holds src atom0
    float seqs       = __shfl_sync(FULL, f4s.w, 4);    // lane 4 holds src atom1
    float noised_dst = __shfl_sync(FULL, f4d.w, 0);    // lane 0 holds dst atom0
    float seqd       = __shfl_sync(FULL, f4d.w, 1);    // lane 1 holds dst atom1

    float keep_src = 1.f - noised_src;
    float keep_dst = 1.f - noised_dst;
    int hot_src = __float_as_int(seqs) + 2;    // one-hot pos within row, [2,22]
    int hot_dst = __float_as_int(seqd) + 23;   // one-hot pos within row, [23,43]

    float* __restrict__ row = out + (size_t)e * FEAT;

    // ---- region A: [0..43] flags + one-hots via 64-bit hot-mask ----
    // bit b of mask64 set <=> row[b] == 1 (one-hot kept). bits 0,1 never set
    // (hot_src >= 2), patched by lane 0 with the noised flags.
    if (lane < 11) {
        unsigned long long mask64 =
            ((unsigned long long)(keep_src != 0.f) << hot_src) |
            ((unsigned long long)(keep_dst != 0.f) << hot_dst);
        unsigned nib = (unsigned)(mask64 >> (4 * lane)) & 0xFu;
        float4 v4;
        v4.x = (nib & 1u) ? 1.f : 0.f;
        v4.y = (nib & 2u) ? 1.f : 0.f;
        v4.z = (nib & 4u) ? 1.f : 0.f;
        v4.w = (nib & 8u) ? 1.f : 0.f;
        if (lane == 0) { v4.x = noised_dst; v4.y = noised_src; }
        __stcs((float4*)(row + 4 * lane), v4);
    }

    // ---- region B: [44..299] RBF of 16 dists, 16 bins each ----
    // lanes 0-15 hold src atom (lane>>2) and dst atom (lane&3) in registers:
    // each computes its distance (MUFU.RSQ fast path); two dense STG.128
    // sweeps cover [44..171] and [172..299]. Bins via geometric recurrence.
    float dx = f4s.x - f4d.x + EPSV;
    float dy = f4s.y - f4d.y + EPSV;
    float dz = f4s.z - f4d.z + EPSV;
    float d2 = dx * dx + dy * dy + dz * dz;
    float D = rsqrtf(d2) * d2;              // sqrt via MUFU.RSQ + FMUL

    float mu0 = 2.0f + (float)(4 * (lane & 3)) * (20.0f / 15.0f);
    {
        // sweep 1: lane L -> floats [44+4L..47+4L], pair = L>>2, bins 4*(L&3)..+3
        float Da = __shfl_sync(FULL, D, lane >> 2);
        float z0 = (Da - mu0) * 0.8f;
        float r0 = __expf(-z0 * z0);
        float g  = __expf(fminf(2.0f * RBF_DELTA * z0 - RBF_DSQ, 80.f));
        float r1 = r0 * g; g *= RBF_C;
        float r2 = r1 * g; g *= RBF_C;
        float r3 = r2 * g;
        __stcs((float4*)(row + 44 + 4 * lane), make_float4(r0, r1, r2, r3));

        // sweep 2: lane L -> floats [172+4L..175+4L], pair = 8 + (L>>2)
        float Db = __shfl_sync(FULL, D, 8 + (lane >> 2));
        z0 = (Db - mu0) * 0.8f;
        r0 = __expf(-z0 * z0);
        g  = __expf(fminf(2.0f * RBF_DELTA * z0 - RBF_DSQ, 80.f));
        r1 = r0 * g; g *= RBF_C;
        r2 = r1 * g; g *= RBF_C;
        r3 = r2 * g;
        __stcs((float4*)(row + 172 + 4 * lane), make_float4(r0, r1, r2, r3));
    }

    // ---- region C: [300..315] positional enc from precomputed table ----
    if (lane < 16) {
        __stcs(row + 300 + lane, pv);
    }

    // ---- regions D+E fused: [316..339] one predicated STG over 24 lanes ----
    // lanes 0..11:  src local frame (prefetched) * keep_src
    // lanes 12..23: dst backbone in src frame * keep_dst, operands via shuffle:
    //   acc = sum_jj R[jj,ii] * (bb_dst[kk][jj] - t[jj])
    //   R[jj,ii] = comp jj of column chunk ii (lane ii)
    //   bb_dst[kk][jj] = comp jj of f4d on lane kk
    //   t[jj] = comp jj of chunk 3 (lane 3)
    {
        int l  = max(lane - 12, 0);
        int kk = min(l / 3, 3);
        int ii = l - 3 * (l / 3);
        float acc = 0.f;
        {   // jj = 0
            float bj = __shfl_sync(FULL, f4d.x, kk);
            float rj = __shfl_sync(FULL, f4rt.x, ii);
            float tj = __shfl_sync(FULL, f4rt.x, 3);
            acc += rj * (bj - tj);
        }
        {   // jj = 1
            float bj = __shfl_sync(FULL, f4d.y, kk);
            float rj = __shfl_sync(FULL, f4rt.y, ii);
            float tj = __shfl_sync(FULL, f4rt.y, 3);
            acc += rj * (bj - tj);
        }
        {   // jj = 2
            float bj = __shfl_sync(FULL, f4d.z, kk);
            float rj = __shfl_sync(FULL, f4rt.z, ii);
            float tj = __shfl_sync(FULL, f4rt.z, 3);
            acc += rj * (bj - tj);
        }
        if (lane < 24) {
            float v = (lane < 12) ? loc * keep_src : acc * keep_dst;
            __stcs(row + 316 + lane, v);
        }
    }
}

// ---------------- launch ----------------
extern "C" void kernel_launch(void* const* d_in, const int* in_sizes, int n_in,
                              void* d_out, int out_size) {
    const float* atom14 = (const float*)d_in[0];
    const float* rigids = (const float*)d_in[1];
    const int*   seq    = (const int*)d_in[2];
    const void*  mask   = d_in[3];
    const int*   eidx   = (const int*)d_in[4];
    float* out = (float*)d_out;

    prep_kernel<<<(N_RES + 255) / 256, 256>>>(atom14, rigids, seq, mask);
    edge_kernel<<<N_EDGE / EPB, EPB * 32>>>(eidx, out);
}

// round 11
// speedup vs baseline: 1.0198x; 1.0198x over previous
#include <cuda_runtime.h>
#include <cstdint>

#define N_RES   20000
#define N_EDGE  640000
#define NUM_AA  21
#define FEAT    340
#define EPSV    1e-8f
#define EPB     8          // edges (warps) per block

// ---------------- device scratch (no mallocs allowed) ----------------
// g_bb4[r*4+k] = atom k (n,ca,c,cb); w-lanes carry metadata:
//   atom0.w = noised flag (0/1), atom1.w = int_as_float(seq)
__device__ float4 g_bb4[N_RES * 4];
// g_Rt4[r*4+c], c=0..2: column c of R = (R[0,c], R[1,c], R[2,c], 0)
//               c=3:    (t0, t1, t2, 0)
__device__ float4 g_Rt4[N_RES * 4];
__device__ float  g_local[N_RES * 12];  // R^T (bb - t)
// positional-encoding table: row (d+19999) = [cos(d*f0..f7), sin(d*f0..f7)]
__device__ float  g_pos[40224 * 16];

__constant__ float c_freq[8] = {
    1.0f, 0.31622776601683794f, 0.1f, 0.03162277660168379f,
    0.01f, 0.0031622776601683794f, 0.001f, 0.00031622776601683794f
};

#define RBF_DELTA 1.0666666666666667f    /* (4/3)*0.8 */
#define RBF_DSQ   1.1377777777777778f    /* delta^2 */
#define RBF_C     0.10274027f            /* exp(-2*delta^2) */

// ---------------- prep: mask dtype detection + residue geometry + pos table ----------------
// Mask dtype detection per-block from the first 512 words (= 2048 bytes,
// in-bounds under every interpretation of the 20000-element mask):
//   int32 0/1 mask   -> words all in {0,1}
//   float32 0/1 mask -> words all in {0, 0x3F800000}
//   packed bool      -> neither (P(ambiguous) = 8^-512 ~ 0)
__global__ void prep_kernel(const float* __restrict__ atom14,
                            const float* __restrict__ rig,
                            const int*   __restrict__ seq,
                            const void*  __restrict__ mask) {
    __shared__ int s_not01, s_notf;
    if (threadIdx.x == 0) { s_not01 = 0; s_notf = 0; }
    __syncthreads();
    {
        const unsigned int* mw = (const unsigned int*)mask;
        unsigned int v0 = mw[threadIdx.x];
        unsigned int v1 = mw[threadIdx.x + 256];
        int not01 = (v0 > 1u) | (v1 > 1u);
        int notf  = ((v0 != 0u && v0 != 0x3F800000u) ||
                     (v1 != 0u && v1 != 0x3F800000u));
        if (not01) atomicOr(&s_not01, 1);
        if (notf)  atomicOr(&s_notf, 1);
    }
    __syncthreads();
    int kind;                                // 0=bool(u8), 1=int32, 2=float32
    if (!s_notf)       kind = 2;
    else if (!s_not01) kind = 1;
    else               kind = 0;

    int tid = blockIdx.x * blockDim.x + threadIdx.x;   // 0 .. 20223

    // ---- positional table: rows tid and tid+20000 (fast HW sin/cos) ----
    #pragma unroll
    for (int half = 0; half < 2; half++) {
        int rrow = tid + half * 20000;
        float dp = (float)(rrow - 19999);
        #pragma unroll
        for (int k = 0; k < 8; k++) {
            float ang = dp * c_freq[k];
            g_pos[rrow * 16 + k]     = __cosf(ang);
            g_pos[rrow * 16 + 8 + k] = __sinf(ang);
        }
    }

    int r = tid;
    if (r >= N_RES) return;

    const float* a = atom14 + (size_t)r * 42;   // 14 atoms * 3
    float n0 = a[0], n1 = a[1], n2 = a[2];
    float ca0 = a[3], ca1 = a[4], ca2 = a[5];
    float c0 = a[6], c1 = a[7], c2 = a[8];

    float b0 = ca0 - n0, b1 = ca1 - n1, b2 = ca2 - n2;
    float e0 = c0 - ca0, e1 = c1 - ca1, e2 = c2 - ca2;
    float ax = b1 * e2 - b2 * e1;
    float ay = b2 * e0 - b0 * e2;
    float az = b0 * e1 - b1 * e0;
    float cb0 = -0.58273431f * ax + 0.56802827f * b0 - 0.54067466f * e0 + ca0;
    float cb1 = -0.58273431f * ay + 0.56802827f * b1 - 0.54067466f * e1 + ca1;
    float cb2 = -0.58273431f * az + 0.56802827f * b2 - 0.54067466f * e2 + ca2;

    float noised;
    if (kind == 0)      noised = ((const unsigned char*)mask)[r] ? 1.f : 0.f;
    else if (kind == 1) noised = ((const int*)mask)[r] ? 1.f : 0.f;
    else                noised = (((const float*)mask)[r] != 0.f) ? 1.f : 0.f;

    float bb[12] = { n0, n1, n2, ca0, ca1, ca2, c0, c1, c2, cb0, cb1, cb2 };
    g_bb4[r * 4 + 0] = make_float4(n0, n1, n2, noised);
    g_bb4[r * 4 + 1] = make_float4(ca0, ca1, ca2, __int_as_float(seq[r]));
    g_bb4[r * 4 + 2] = make_float4(c0, c1, c2, 0.f);
    g_bb4[r * 4 + 3] = make_float4(cb0, cb1, cb2, 0.f);

    const float* q = rig + (size_t)r * 7;
    float qw = q[0], qx = q[1], qy = q[2], qz = q[3];
    float inv = rsqrtf(qw * qw + qx * qx + qy * qy + qz * qz);
    qw *= inv; qx *= inv; qy *= inv; qz *= inv;

    float R[9];
    R[0] = 1.f - 2.f * (qy * qy + qz * qz);
    R[1] = 2.f * (qx * qy - qw * qz);
    R[2] = 2.f * (qx * qz + qw * qy);
    R[3] = 2.f * (qx * qy + qw * qz);
    R[4] = 1.f - 2.f * (qx * qx + qz * qz);
    R[5] = 2.f * (qy * qz - qw * qx);
    R[6] = 2.f * (qx * qz - qw * qy);
    R[7] = 2.f * (qy * qz + qw * qx);
    R[8] = 1.f - 2.f * (qx * qx + qy * qy);
    float t0 = q[4], t1 = q[5], t2 = q[6];

    // column-major chunks: chunk c = (R[0,c], R[1,c], R[2,c], 0); chunk 3 = t
    g_Rt4[r * 4 + 0] = make_float4(R[0], R[3], R[6], 0.f);
    g_Rt4[r * 4 + 1] = make_float4(R[1], R[4], R[7], 0.f);
    g_Rt4[r * 4 + 2] = make_float4(R[2], R[5], R[8], 0.f);
    g_Rt4[r * 4 + 3] = make_float4(t0, t1, t2, 0.f);

    // local[k][i] = sum_j R[j][i] * (bb[k][j] - t[j])
    #pragma unroll
    for (int k = 0; k < 4; k++) {
        float vx = bb[k * 3 + 0] - t0;
        float vy = bb[k * 3 + 1] - t1;
        float vz = bb[k * 3 + 2] - t2;
        #pragma unroll
        for (int i = 0; i < 3; i++) {
            g_local[r * 12 + k * 3 + i] = R[0 + i] * vx + R[3 + i] * vy + R[6 + i] * vz;
        }
    }
}

// ---------------- per-edge feature kernel: 1 warp / edge, zero smem ----------------
__global__ __launch_bounds__(EPB * 32) void edge_kernel(
    const int* __restrict__ eidx,     // [2, N_EDGE]: row0=dst, row1=src
    float* __restrict__ out) {

    const unsigned FULL = 0xFFFFFFFFu;
    int lane = threadIdx.x & 31;
    int e    = blockIdx.x * EPB + (threadIdx.x >> 5);

    int dst = eidx[e];
    int src = eidx[N_EDGE + e];

    // gather index plan:
    //   lanes 0-15 : RBF distance pair (src atom lane>>2, dst atom lane&3)
    //   lanes 20-31: region E element la = lane-20 (kk = la/3 dst atom,
    //                ii = la%3 R-column); lanes 16-19 duplicate la=0
    int la = min(max(lane - 20, 0), 11);
    int ekk = la / 3;                 // dst atom for region E
    int eii = la - 3 * ekk;           // R column for region E
    int ai_d = (lane < 16) ? (lane & 3) : ekk;       // f4d atom index
    int ci_r = (lane < 16) ? (lane & 3) : eii;       // f4rt chunk index

    // register gathers (broadcast-heavy, L2-resident tables)
    float4 f4s = g_bb4[src * 4 + ((lane >> 2) & 3)];
    float4 f4d = g_bb4[dst * 4 + ai_d];
    float4 f4rt = g_Rt4[src * 4 + ci_r];             // lane 3 holds t chunk
    float loc = g_local[src * 12 + min(lane, 11)];   // lanes 0-11 meaningful
    float pv  = g_pos[((dst - src) + 19999) * 16 + (lane & 15)];  // pos enc row

    // metadata via shuffle from w-lanes (no extra loads)
    float noised_src = __shfl_sync(FULL, f4s.w, 0);    // lane 0 holds src atom0
    float seqs       = __shfl_sync(FULL, f4s.w, 4);    // lane 4 holds src atom1
    float noised_dst = __shfl_sync(FULL, f4d.w, 0);    // lane 0 holds dst atom0
    float seqd       = __shfl_sync(FULL, f4d.w, 1);    // lane 1 holds dst atom1

    float keep_src = 1.f - noised_src;
    float keep_dst = 1.f - noised_dst;
    int hot_src = __float_as_int(seqs) + 2;    // one-hot pos within row, [2,22]
    int hot_dst = __float_as_int(seqd) + 23;   // one-hot pos within row, [23,43]

    float* __restrict__ row = out + (size_t)e * FEAT;

    // ---- region A: [0..43] flags + one-hots via 64-bit hot-mask ----
    if (lane < 11) {
        unsigned long long mask64 =
            ((unsigned long long)(keep_src != 0.f) << hot_src) |
            ((unsigned long long)(keep_dst != 0.f) << hot_dst);
        unsigned nib = (unsigned)(mask64 >> (4 * lane)) & 0xFu;
        float4 v4;
        v4.x = (nib & 1u) ? 1.f : 0.f;
        v4.y = (nib & 2u) ? 1.f : 0.f;
        v4.z = (nib & 4u) ? 1.f : 0.f;
        v4.w = (nib & 8u) ? 1.f : 0.f;
        if (lane == 0) { v4.x = noised_dst; v4.y = noised_src; }
        __stcs((float4*)(row + 4 * lane), v4);
    }

    // ---- region B: [44..299] RBF of 16 dists, 16 bins each ----
    // lanes 0-15 hold src atom (lane>>2) and dst atom (lane&3) in registers:
    // each computes its distance (MUFU.RSQ fast path); two dense STG.128
    // sweeps cover [44..171] and [172..299]. Bins via geometric recurrence.
    float dx = f4s.x - f4d.x + EPSV;
    float dy = f4s.y - f4d.y + EPSV;
    float dz = f4s.z - f4d.z + EPSV;
    float d2 = dx * dx + dy * dy + dz * dz;
    float D = rsqrtf(d2) * d2;              // sqrt via MUFU.RSQ + FMUL

    float mu0 = 2.0f + (float)(4 * (lane & 3)) * (20.0f / 15.0f);
    {
        // sweep 1: lane L -> floats [44+4L..47+4L], pair = L>>2, bins 4*(L&3)..+3
        float Da = __shfl_sync(FULL, D, lane >> 2);
        float z0 = (Da - mu0) * 0.8f;
        float r0 = __expf(-z0 * z0);
        float g  = __expf(fminf(2.0f * RBF_DELTA * z0 - RBF_DSQ, 80.f));
        float r1 = r0 * g; g *= RBF_C;
        float r2 = r1 * g; g *= RBF_C;
        float r3 = r2 * g;
        __stcs((float4*)(row + 44 + 4 * lane), make_float4(r0, r1, r2, r3));

        // sweep 2: lane L -> floats [172+4L..175+4L], pair = 8 + (L>>2)
        float Db = __shfl_sync(FULL, D, 8 + (lane >> 2));
        z0 = (Db - mu0) * 0.8f;
        r0 = __expf(-z0 * z0);
        g  = __expf(fminf(2.0f * RBF_DELTA * z0 - RBF_DSQ, 80.f));
        r1 = r0 * g; g *= RBF_C;
        r2 = r1 * g; g *= RBF_C;
        r3 = r2 * g;
        __stcs((float4*)(row + 172 + 4 * lane), make_float4(r0, r1, r2, r3));
    }

    // ---- region C: [300..315] positional enc from precomputed table ----
    if (lane < 16) {
        __stcs(row + 300 + lane, pv);
    }

    // ---- regions D+E: [316..339] single predicated STG ----
    // lanes 0..11:  [316..327] src local frame (prefetched) * keep_src
    // lanes 20..31: [328..339] dst backbone in src frame * keep_dst
    //   acc = dot(R column eii, bb_dst[ekk] - t); R column + atom held locally,
    //   t shuffled from lane 3 (f4rt chunk 3).
    {
        float tx = __shfl_sync(FULL, f4rt.x, 3);
        float ty = __shfl_sync(FULL, f4rt.y, 3);
        float tz = __shfl_sync(FULL, f4rt.z, 3);
        float acc = f4rt.x * (f4d.x - tx)
                  + f4rt.y * (f4d.y - ty)
                  + f4rt.z * (f4d.z - tz);
        bool on = (lane < 12) | (lane >= 20);
        float v = (lane < 12) ? loc * keep_src : acc * keep_dst;
        int off = (lane < 12) ? (316 + lane) : (308 + lane);
        if (on) __stcs(row + off, v);
    }
}

// ---------------- launch ----------------
extern "C" void kernel_launch(void* const* d_in, const int* in_sizes, int n_in,
                              void* d_out, int out_size) {
    const float* atom14 = (const float*)d_in[0];
    const float* rigids = (const float*)d_in[1];
    const int*   seq    = (const int*)d_in[2];
    const void*  mask   = d_in[3];
    const int*   eidx   = (const int*)d_in[4];
    float* out = (float*)d_out;

    prep_kernel<<<(N_RES + 255) / 256, 256>>>(atom14, rigids, seq, mask);
    edge_kernel<<<N_EDGE / EPB, EPB * 32>>>(eidx, out);
}

// round 12
// speedup vs baseline: 1.0537x; 1.0332x over previous
#include <cuda_runtime.h>
#include <cstdint>

#define N_RES   20000
#define N_EDGE  640000
#define NUM_AA  21
#define FEAT    340
#define EPSV    1e-8f
#define EPB     8          // edges (warps) per block

// ---------------- device scratch (no mallocs allowed) ----------------
// g_bb4[r*4+k] = atom k (n,ca,c,cb); w-lanes carry metadata:
//   atom0.w = noised flag (0/1), atom1.w = int_as_float(seq)
__device__ float4 g_bb4[N_RES * 4];
// g_Rt4[r*4+c], c=0..2: column c of R = (R[0,c], R[1,c], R[2,c], 0)
//               c=3:    (t0, t1, t2, 0)
__device__ float4 g_Rt4[N_RES * 4];
__device__ float  g_local[N_RES * 12];  // R^T (bb - t)

__constant__ float c_freq[8] = {
    1.0f, 0.31622776601683794f, 0.1f, 0.03162277660168379f,
    0.01f, 0.0031622776601683794f, 0.001f, 0.00031622776601683794f
};

#define RBF_DELTA 1.0666666666666667f    /* (4/3)*0.8 */
#define RBF_DSQ   1.1377777777777778f    /* delta^2 */
#define RBF_C     0.10274027f            /* exp(-2*delta^2) */

// ---------------- prep: mask dtype detection + residue geometry ----------------
// Mask dtype detection per-block from the first 512 words (= 2048 bytes,
// in-bounds under every interpretation of the 20000-element mask):
//   int32 0/1 mask   -> words all in {0,1}
//   float32 0/1 mask -> words all in {0, 0x3F800000}
//   packed bool      -> neither (P(ambiguous) = 8^-512 ~ 0)
__global__ void prep_kernel(const float* __restrict__ atom14,
                            const float* __restrict__ rig,
                            const int*   __restrict__ seq,
                            const void*  __restrict__ mask) {
    __shared__ int s_not01, s_notf;
    if (threadIdx.x == 0) { s_not01 = 0; s_notf = 0; }
    __syncthreads();
    {
        const unsigned int* mw = (const unsigned int*)mask;
        unsigned int v0 = mw[threadIdx.x];
        unsigned int v1 = mw[threadIdx.x + 256];
        int not01 = (v0 > 1u) | (v1 > 1u);
        int notf  = ((v0 != 0u && v0 != 0x3F800000u) ||
                     (v1 != 0u && v1 != 0x3F800000u));
        if (not01) atomicOr(&s_not01, 1);
        if (notf)  atomicOr(&s_notf, 1);
    }
    __syncthreads();
    int kind;                                // 0=bool(u8), 1=int32, 2=float32
    if (!s_notf)       kind = 2;
    else if (!s_not01) kind = 1;
    else               kind = 0;

    int r = blockIdx.x * blockDim.x + threadIdx.x;
    if (r >= N_RES) return;

    const float* a = atom14 + (size_t)r * 42;   // 14 atoms * 3
    float n0 = a[0], n1 = a[1], n2 = a[2];
    float ca0 = a[3], ca1 = a[4], ca2 = a[5];
    float c0 = a[6], c1 = a[7], c2 = a[8];

    float b0 = ca0 - n0, b1 = ca1 - n1, b2 = ca2 - n2;
    float e0 = c0 - ca0, e1 = c1 - ca1, e2 = c2 - ca2;
    float ax = b1 * e2 - b2 * e1;
    float ay = b2 * e0 - b0 * e2;
    float az = b0 * e1 - b1 * e0;
    float cb0 = -0.58273431f * ax + 0.56802827f * b0 - 0.54067466f * e0 + ca0;
    float cb1 = -0.58273431f * ay + 0.56802827f * b1 - 0.54067466f * e1 + ca1;
    float cb2 = -0.58273431f * az + 0.56802827f * b2 - 0.54067466f * e2 + ca2;

    float noised;
    if (kind == 0)      noised = ((const unsigned char*)mask)[r] ? 1.f : 0.f;
    else if (kind == 1) noised = ((const int*)mask)[r] ? 1.f : 0.f;
    else                noised = (((const float*)mask)[r] != 0.f) ? 1.f : 0.f;

    float bb[12] = { n0, n1, n2, ca0, ca1, ca2, c0, c1, c2, cb0, cb1, cb2 };
    g_bb4[r * 4 + 0] = make_float4(n0, n1, n2, noised);
    g_bb4[r * 4 + 1] = make_float4(ca0, ca1, ca2, __int_as_float(seq[r]));
    g_bb4[r * 4 + 2] = make_float4(c0, c1, c2, 0.f);
    g_bb4[r * 4 + 3] = make_float4(cb0, cb1, cb2, 0.f);

    const float* q = rig + (size_t)r * 7;
    float qw = q[0], qx = q[1], qy = q[2], qz = q[3];
    float inv = rsqrtf(qw * qw + qx * qx + qy * qy + qz * qz);
    qw *= inv; qx *= inv; qy *= inv; qz *= inv;

    float R[9];
    R[0] = 1.f - 2.f * (qy * qy + qz * qz);
    R[1] = 2.f * (qx * qy - qw * qz);
    R[2] = 2.f * (qx * qz + qw * qy);
    R[3] = 2.f * (qx * qy + qw * qz);
    R[4] = 1.f - 2.f * (qx * qx + qz * qz);
    R[5] = 2.f * (qy * qz - qw * qx);
    R[6] = 2.f * (qx * qz - qw * qy);
    R[7] = 2.f * (qy * qz + qw * qx);
    R[8] = 1.f - 2.f * (qx * qx + qy * qy);
    float t0 = q[4], t1 = q[5], t2 = q[6];

    // column-major chunks: chunk c = (R[0,c], R[1,c], R[2,c], 0); chunk 3 = t
    g_Rt4[r * 4 + 0] = make_float4(R[0], R[3], R[6], 0.f);
    g_Rt4[r * 4 + 1] = make_float4(R[1], R[4], R[7], 0.f);
    g_Rt4[r * 4 + 2] = make_float4(R[2], R[5], R[8], 0.f);
    g_Rt4[r * 4 + 3] = make_float4(t0, t1, t2, 0.f);

    // local[k][i] = sum_j R[j][i] * (bb[k][j] - t[j])
    #pragma unroll
    for (int k = 0; k < 4; k++) {
        float vx = bb[k * 3 + 0] - t0;
        float vy = bb[k * 3 + 1] - t1;
        float vz = bb[k * 3 + 2] - t2;
        #pragma unroll
        for (int i = 0; i < 3; i++) {
            g_local[r * 12 + k * 3 + i] = R[0 + i] * vx + R[3 + i] * vy + R[6 + i] * vz;
        }
    }
}

// ---------------- per-edge feature kernel: 1 warp / edge, zero smem ----------------
__global__ __launch_bounds__(EPB * 32) void edge_kernel(
    const int* __restrict__ eidx,     // [2, N_EDGE]: row0=dst, row1=src
    float* __restrict__ out) {

    const unsigned FULL = 0xFFFFFFFFu;
    int lane = threadIdx.x & 31;
    int e    = blockIdx.x * EPB + (threadIdx.x >> 5);

    int dst = eidx[e];
    int src = eidx[N_EDGE + e];

    // gather index plan:
    //   lanes 0-15 : RBF distance pair (src atom lane>>2, dst atom lane&3)
    //   lanes 20-31: region E element la = lane-20 (kk = la/3 dst atom,
    //                ii = la%3 R-column); lanes 16-19 duplicate la=0
    int la = min(max(lane - 20, 0), 11);
    int ekk = la / 3;                 // dst atom for region E
    int eii = la - 3 * ekk;           // R column for region E
    int ai_d = (lane < 16) ? (lane & 3) : ekk;       // f4d atom index
    int ci_r = (lane < 16) ? (lane & 3) : eii;       // f4rt chunk index

    // register gathers (broadcast-heavy, L2-resident tables)
    float4 f4s = g_bb4[src * 4 + ((lane >> 2) & 3)];
    float4 f4d = g_bb4[dst * 4 + ai_d];
    float4 f4rt = g_Rt4[src * 4 + ci_r];             // lane 3 holds t chunk
    float loc = g_local[src * 12 + min(lane, 11)];   // lanes 0-11 meaningful

    // metadata via shuffle from w-lanes (no extra loads)
    float noised_src = __shfl_sync(FULL, f4s.w, 0);    // lane 0 holds src atom0
    float seqs       = __shfl_sync(FULL, f4s.w, 4);    // lane 4 holds src atom1
    float noised_dst = __shfl_sync(FULL, f4d.w, 0);    // lane 0 holds dst atom0
    float seqd       = __shfl_sync(FULL, f4d.w, 1);    // lane 1 holds dst atom1

    float keep_src = 1.f - noised_src;
    float keep_dst = 1.f - noised_dst;
    int hot_src = __float_as_int(seqs) + 2;    // one-hot pos within row, [2,22]
    int hot_dst = __float_as_int(seqd) + 23;   // one-hot pos within row, [23,43]

    float* __restrict__ row = out + (size_t)e * FEAT;

    // ---- region A: [0..43] flags + one-hots via 64-bit hot-mask ----
    if (lane < 11) {
        unsigned long long mask64 =
            ((unsigned long long)(keep_src != 0.f) << hot_src) |
            ((unsigned long long)(keep_dst != 0.f) << hot_dst);
        unsigned nib = (unsigned)(mask64 >> (4 * lane)) & 0xFu;
        float4 v4;
        v4.x = (nib & 1u) ? 1.f : 0.f;
        v4.y = (nib & 2u) ? 1.f : 0.f;
        v4.z = (nib & 4u) ? 1.f : 0.f;
        v4.w = (nib & 8u) ? 1.f : 0.f;
        if (lane == 0) { v4.x = noised_dst; v4.y = noised_src; }
        __stcs((float4*)(row + 4 * lane), v4);
    }

    // ---- region B: [44..299] RBF of 16 dists, 16 bins each ----
    // lanes 0-15 hold src atom (lane>>2) and dst atom (lane&3) in registers:
    // each computes its distance (MUFU.RSQ fast path); two dense STG.128
    // sweeps cover [44..171] and [172..299]. Bins via geometric recurrence.
    float dx = f4s.x - f4d.x + EPSV;
    float dy = f4s.y - f4d.y + EPSV;
    float dz = f4s.z - f4d.z + EPSV;
    float d2 = dx * dx + dy * dy + dz * dz;
    float D = rsqrtf(d2) * d2;              // sqrt via MUFU.RSQ + FMUL

    float mu0 = 2.0f + (float)(4 * (lane & 3)) * (20.0f / 15.0f);
    {
        // sweep 1: lane L -> floats [44+4L..47+4L], pair = L>>2, bins 4*(L&3)..+3
        float Da = __shfl_sync(FULL, D, lane >> 2);
        float z0 = (Da - mu0) * 0.8f;
        float r0 = __expf(-z0 * z0);
        float g  = __expf(fminf(2.0f * RBF_DELTA * z0 - RBF_DSQ, 80.f));
        float r1 = r0 * g; g *= RBF_C;
        float r2 = r1 * g; g *= RBF_C;
        float r3 = r2 * g;
        __stcs((float4*)(row + 44 + 4 * lane), make_float4(r0, r1, r2, r3));

        // sweep 2: lane L -> floats [172+4L..175+4L], pair = 8 + (L>>2)
        float Db = __shfl_sync(FULL, D, 8 + (lane >> 2));
        z0 = (Db - mu0) * 0.8f;
        r0 = __expf(-z0 * z0);
        g  = __expf(fminf(2.0f * RBF_DELTA * z0 - RBF_DSQ, 80.f));
        r1 = r0 * g; g *= RBF_C;
        r2 = r1 * g; g *= RBF_C;
        r3 = r2 * g;
        __stcs((float4*)(row + 172 + 4 * lane), make_float4(r0, r1, r2, r3));
    }

    // ---- region C: [300..315] positional enc (fast sin/cos, HW range red.) ----
    if (lane < 16) {
        float dp = (float)(dst - src);
        float ang = dp * c_freq[lane & 7];
        __stcs(row + 300 + lane, (lane < 8) ? __cosf(ang) : __sinf(ang));
    }

    // ---- regions D+E: [316..339] single predicated STG ----
    // lanes 0..11:  [316..327] src local frame (prefetched) * keep_src
    // lanes 20..31: [328..339] dst backbone in src frame * keep_dst
    //   acc = dot(R column eii, bb_dst[ekk] - t); R column + atom held locally,
    //   t shuffled from lane 3 (f4rt chunk 3).
    {
        float tx = __shfl_sync(FULL, f4rt.x, 3);
        float ty = __shfl_sync(FULL, f4rt.y, 3);
        float tz = __shfl_sync(FULL, f4rt.z, 3);
        float acc = f4rt.x * (f4d.x - tx)
                  + f4rt.y * (f4d.y - ty)
                  + f4rt.z * (f4d.z - tz);
        bool on = (lane < 12) | (lane >= 20);
        float v = (lane < 12) ? loc * keep_src : acc * keep_dst;
        int off = (lane < 12) ? (316 + lane) : (308 + lane);
        if (on) __stcs(row + off, v);
    }
}

// ---------------- launch ----------------
extern "C" void kernel_launch(void* const* d_in, const int* in_sizes, int n_in,
                              void* d_out, int out_size) {
    const float* atom14 = (const float*)d_in[0];
    const float* rigids = (const float*)d_in[1];
    const int*   seq    = (const int*)d_in[2];
    const void*  mask   = d_in[3];
    const int*   eidx   = (const int*)d_in[4];
    float* out = (float*)d_out;

    prep_kernel<<<(N_RES + 255) / 256, 256>>>(atom14, rigids, seq, mask);
    edge_kernel<<<N_EDGE / EPB, EPB * 32>>>(eidx, out);
}